// round 9
// baseline (speedup 1.0000x reference)
#include <cuda_runtime.h>
#include <cuda_fp16.h>
#include <cstdint>

// Problem constants
#define BB 64
#define SS 1024
#define CC 512
#define SC (SS*CC)
#define NN (BB*CC)          // 32768 = total N of the big GEMM
#define EPS 1e-5f
#define RED_CHUNKS 64
#define BK 64               // k-tile (halves)
#define NT (SS / BK)        // 16 k-tiles

// Scratch (device globals; 16B-aligned for cp.async / uint4)
__device__ float2 g_partials[BB * RED_CHUNKS];
__device__ float2 g_stats[BB];
// K-panel layouts: [(kt*ROWS + row)*BK + ks], fp16
__device__ __align__(16) __half g_Hp[(size_t)NN * SS];     // B panels (64MB)
__device__ __align__(16) __half g_Wh[(size_t)SS * SS];     // A panels (2MB)

// ---------------------------------------------------------------------------
// helpers
// ---------------------------------------------------------------------------
__device__ __forceinline__ uint32_t smem_to_u32(const void* p) {
    uint32_t a;
    asm("{ .reg .u64 t; cvta.to.shared.u64 t, %1; cvt.u32.u64 %0, t; }" : "=r"(a) : "l"(p));
    return a;
}
__device__ __forceinline__ void ldmatrix_x4(uint32_t& r0, uint32_t& r1,
                                            uint32_t& r2, uint32_t& r3, uint32_t addr) {
    asm volatile("ldmatrix.sync.aligned.m8n8.x4.shared.b16 {%0,%1,%2,%3}, [%4];"
                 : "=r"(r0), "=r"(r1), "=r"(r2), "=r"(r3) : "r"(addr));
}
__device__ __forceinline__ void mma_f16(float* d, const uint32_t* a,
                                        uint32_t b0, uint32_t b1) {
    asm volatile(
        "mma.sync.aligned.m16n8k16.row.col.f32.f16.f16.f32 "
        "{%0,%1,%2,%3}, {%4,%5,%6,%7}, {%8,%9}, {%0,%1,%2,%3};"
        : "+f"(d[0]), "+f"(d[1]), "+f"(d[2]), "+f"(d[3])
        : "r"(a[0]), "r"(a[1]), "r"(a[2]), "r"(a[3]), "r"(b0), "r"(b1));
}
__device__ __forceinline__ void cp16(uint32_t dst, const void* src) {
    asm volatile("cp.async.cg.shared.global [%0], [%1], 16;" :: "r"(dst), "l"(src));
}
#define CP_COMMIT() asm volatile("cp.async.commit_group;" ::: "memory")
#define CP_WAIT1()  asm volatile("cp.async.wait_group 1;" ::: "memory")

__device__ __forceinline__ uint32_t pack2(float a, float b) {
    __half2 h = __floats2half2_rn(a, b);
    return *reinterpret_cast<uint32_t*>(&h);
}

// ---------------------------------------------------------------------------
// Kernel 1 (fused): blocks [0,4096): per-batch partial sums.
//                   blocks [4096,5120): convert W -> g_Wh fp16 K-panels.
// 256 threads everywhere. Deterministic.
// ---------------------------------------------------------------------------
__global__ void reduce_conv_kernel(const float* __restrict__ x,
                                   const float* __restrict__ W) {
    if (blockIdx.x < BB * RED_CHUNKS) {
        const int b     = blockIdx.x / RED_CHUNKS;
        const int chunk = blockIdx.x % RED_CHUNKS;
        const int n4    = SC / RED_CHUNKS / 4;
        const float4* px = reinterpret_cast<const float4*>(x + (size_t)b * SC) + (size_t)chunk * n4;

        float s = 0.f, sq = 0.f;
        for (int i = threadIdx.x; i < n4; i += blockDim.x) {
            float4 v = px[i];
            s  += v.x + v.y + v.z + v.w;
            sq += v.x*v.x + v.y*v.y + v.z*v.z + v.w*v.w;
        }
        __shared__ float ss[8], ssq[8];
        #pragma unroll
        for (int o = 16; o > 0; o >>= 1) {
            s  += __shfl_down_sync(0xffffffff, s,  o);
            sq += __shfl_down_sync(0xffffffff, sq, o);
        }
        if ((threadIdx.x & 31) == 0) { ss[threadIdx.x >> 5] = s; ssq[threadIdx.x >> 5] = sq; }
        __syncthreads();
        if (threadIdx.x == 0) {
            float ts = 0.f, tsq = 0.f;
            #pragma unroll
            for (int w = 0; w < 8; w++) { ts += ss[w]; tsq += ssq[w]; }
            g_partials[blockIdx.x] = make_float2(ts, tsq);
        }
    } else {
        // convert W (fp32 [m][s]) -> g_Wh fp16 K-panels [(kt*1024+m)*BK+ks]
        __shared__ float tile[32][33];
        const int cw = blockIdx.x - BB * RED_CHUNKS;   // 0..1023
        const int m0 = (cw >> 5) * 32;
        const int s0 = (cw & 31) * 32;
        const int tx = threadIdx.x & 31;
        const int ty = threadIdx.x >> 5;
        #pragma unroll
        for (int i = 0; i < 4; i++)
            tile[ty + i * 8][tx] = W[(size_t)(m0 + ty + i * 8) * SS + s0 + tx];
        __syncthreads();
        const int idx = threadIdx.x;
        if (idx < 128) {
            const int m     = idx >> 2;
            const int chunk = idx & 3;
            const int kt    = s0 / BK;            // 64-wide k-tile
            const int ksub  = (s0 & (BK - 1));    // 0 or 32 within the k-tile
            uint4 pk;
            pk.x = pack2(tile[m][chunk*8+0], tile[m][chunk*8+1]);
            pk.y = pack2(tile[m][chunk*8+2], tile[m][chunk*8+3]);
            pk.z = pack2(tile[m][chunk*8+4], tile[m][chunk*8+5]);
            pk.w = pack2(tile[m][chunk*8+6], tile[m][chunk*8+7]);
            *reinterpret_cast<uint4*>(g_Wh + ((size_t)kt * SS + m0 + m) * BK + ksub + chunk * 8) = pk;
        }
    }
}

// ---------------------------------------------------------------------------
// Kernel 2: finalize stats (mu, rstd) per batch.
// ---------------------------------------------------------------------------
__global__ void stats_kernel() {
    int b = threadIdx.x;
    if (b < BB) {
        float s = 0.f, sq = 0.f;
        #pragma unroll 8
        for (int i = 0; i < RED_CHUNKS; i++) {
            float2 p = g_partials[b * RED_CHUNKS + i];
            s += p.x; sq += p.y;
        }
        float mu  = s / (float)SC;
        float var = fmaxf(sq / (float)SC - mu * mu, 0.f);
        g_stats[b] = make_float2(mu, rsqrtf(var + EPS));
    }
}

// ---------------------------------------------------------------------------
// Kernel 3: fused LayerNorm + transpose -> g_Hp K-panels [(kt*NN + n)*BK + ks].
// block (32,8), grid (S/32, C/32, B).
// ---------------------------------------------------------------------------
__global__ void normalize_t_kernel(const float* __restrict__ x,
                                   const float* __restrict__ lnw,
                                   const float* __restrict__ lnb) {
    __shared__ float tile[32][33];     // [s_local][c_local]
    const int b  = blockIdx.z;
    const int s0 = blockIdx.x * 32;
    const int c0 = blockIdx.y * 32;
    const float2 st = g_stats[b];

    #pragma unroll
    for (int i = 0; i < 4; i++) {
        int s = s0 + threadIdx.y + i * 8;
        int c = c0 + threadIdx.x;
        float v  = x  [(size_t)b * SC + (size_t)s * CC + c];
        float w  = lnw[(size_t)s * CC + c];
        float bb = lnb[(size_t)s * CC + c];
        tile[threadIdx.y + i * 8][threadIdx.x] = (v - st.x) * st.y * w + bb;
    }
    __syncthreads();
    const int idx = threadIdx.y * 32 + threadIdx.x;
    if (idx < 128) {
        const int c     = idx >> 2;
        const int chunk = idx & 3;
        const int kt    = s0 / BK;
        const int ksub  = (s0 & (BK - 1));
        const int n     = b * CC + c0 + c;
        uint4 pk;
        pk.x = pack2(tile[chunk*8+0][c], tile[chunk*8+1][c]);
        pk.y = pack2(tile[chunk*8+2][c], tile[chunk*8+3][c]);
        pk.z = pack2(tile[chunk*8+4][c], tile[chunk*8+5][c]);
        pk.w = pack2(tile[chunk*8+6][c], tile[chunk*8+7][c]);
        *reinterpret_cast<uint4*>(g_Hp + ((size_t)kt * NN + n) * BK + ksub + chunk * 8) = pk;
    }
}

// ---------------------------------------------------------------------------
// Kernel 4: fp16 GEMM, fp32 acc. D[1024, 32768] = Wh x Hp^T, K=1024.
// CTA 128(M) x 256(N) x 64(K). 8 warps (2M x 4N), warp 64x64.
// 2-stage cp.async pipeline, 16 k-tiles (half the sync boundaries of BK=32).
// smem rows 144B: 16B-bank = (9r+c) mod 8 -> conflict-free ldmatrix.
// Epilogue: out = x + relu(D + bias).
// ---------------------------------------------------------------------------
#define BM 128
#define BN 256
#define ROWB 144                   // 128B data + 16B pad
#define AST (BM * ROWB)            // 18432 B per A stage
#define BST (BN * ROWB)            // 36864 B per B stage
#define NSTG 2
#define OFF_BS (NSTG * AST)        // B stages base
#define GSMEM (NSTG * (AST + BST)) // 110592 B

__global__ __launch_bounds__(256, 1)
void gemm_f16(const float* __restrict__ linb,
              const float* __restrict__ x, float* __restrict__ out)
{
    extern __shared__ char smem[];
    const uint32_t sb = smem_to_u32(smem);

    const int tid  = threadIdx.x;
    const int lane = tid & 31;
    const int wid  = tid >> 5;
    const int wm   = (wid >> 2) * 64;       // 0 / 64
    const int wn   = (wid & 3) * 64;        // 0..192
    const int m0   = blockIdx.x * BM;
    const int n0   = blockIdx.y * BN;

    float acc[4][8][4];
    #pragma unroll
    for (int i = 0; i < 4; i++)
        #pragma unroll
        for (int j = 0; j < 8; j++)
            #pragma unroll
            for (int k = 0; k < 4; k++) acc[i][j][k] = 0.f;

    // cp.async chunk mapping: rows have 8 x 16B chunks (BK=64 halves = 128B)
    const int ldRow = tid >> 1;              // 0..127
    const int ldPrt = (tid & 1) * 4;         // chunk 0..3 / 4..7

    const __half* Apan = g_Wh + ((size_t)m0) * BK;  // + t*SS*BK per tile
    const __half* Bpan = g_Hp + ((size_t)n0) * BK;  // + t*NN*BK per tile

    #define ISSUE(t, st)                                                          \
        do {                                                                      \
            const __half* asrc = Apan + (size_t)(t) * SS * BK;                    \
            const __half* bsrc = Bpan + (size_t)(t) * NN * BK;                    \
            _Pragma("unroll")                                                     \
            for (int cc = 0; cc < 4; cc++)                                        \
                cp16(sb + (st) * AST + ldRow * ROWB + (ldPrt + cc) * 16,          \
                     asrc + (size_t)ldRow * BK + (ldPrt + cc) * 8);               \
            _Pragma("unroll")                                                     \
            for (int j = 0; j < 2; j++) {                                         \
                int n = ldRow + j * 128;                                          \
                _Pragma("unroll")                                                 \
                for (int cc = 0; cc < 4; cc++)                                    \
                    cp16(sb + OFF_BS + (st) * BST + n * ROWB + (ldPrt + cc) * 16, \
                         bsrc + (size_t)n * BK + (ldPrt + cc) * 8);               \
            }                                                                     \
        } while (0)

    // ldmatrix base addresses
    const int l15 = lane & 15;
    const int lhi = lane >> 4;
    const uint32_t aLd = sb + (wm + l15) * ROWB + lhi * 16;
    const uint32_t bLd = sb + OFF_BS + (wn + l15) * ROWB + lhi * 16;

    // prologue: stages 0,1
    ISSUE(0, 0); CP_COMMIT();
    ISSUE(1, 1); CP_COMMIT();

    for (int t = 0; t < NT; t++) {
        const int st = t & 1;
        CP_WAIT1();                 // tile t arrived (t+1 may pend)
        __syncthreads();

        #pragma unroll
        for (int ks = 0; ks < 4; ks++) {
            uint32_t a[4][4], bm_[4][4];
            #pragma unroll
            for (int i = 0; i < 4; i++)
                ldmatrix_x4(a[i][0], a[i][1], a[i][2], a[i][3],
                            aLd + st * AST + i * 16 * ROWB + ks * 32);
            #pragma unroll
            for (int j = 0; j < 4; j++)
                ldmatrix_x4(bm_[j][0], bm_[j][1], bm_[j][2], bm_[j][3],
                            bLd + st * BST + j * 16 * ROWB + ks * 32);
            #pragma unroll
            for (int i = 0; i < 4; i++)
                #pragma unroll
                for (int j = 0; j < 4; j++) {
                    mma_f16(acc[i][2*j    ], a[i], bm_[j][0], bm_[j][2]);
                    mma_f16(acc[i][2*j + 1], a[i], bm_[j][1], bm_[j][3]);
                }
        }

        __syncthreads();            // all warps done reading stage st
        if (t + 2 < NT) { ISSUE(t + 2, st); CP_COMMIT(); }
    }

    // Epilogue: n -> (batch, channel); whole CTA sits in one batch.
    const int bidx = n0 >> 9;
    const int c0   = n0 & 511;
    const float* xb = x   + (size_t)bidx * SC;
    float*       ob = out + (size_t)bidx * SC;

    #pragma unroll
    for (int i = 0; i < 4; i++) {
        const int t0 = m0 + wm + i * 16 + (lane >> 2);
        const float bias0 = __ldg(linb + t0);
        const float bias1 = __ldg(linb + t0 + 8);
        #pragma unroll
        for (int j = 0; j < 8; j++) {
            const int c = c0 + wn + j * 8 + (lane & 3) * 2;
            float2 xv0 = *reinterpret_cast<const float2*>(xb + (size_t)t0 * CC + c);
            float2 o0;
            o0.x = xv0.x + fmaxf(acc[i][j][0] + bias0, 0.f);
            o0.y = xv0.y + fmaxf(acc[i][j][1] + bias0, 0.f);
            *reinterpret_cast<float2*>(ob + (size_t)t0 * CC + c) = o0;

            float2 xv1 = *reinterpret_cast<const float2*>(xb + (size_t)(t0 + 8) * CC + c);
            float2 o1;
            o1.x = xv1.x + fmaxf(acc[i][j][2] + bias1, 0.f);
            o1.y = xv1.y + fmaxf(acc[i][j][3] + bias1, 0.f);
            *reinterpret_cast<float2*>(ob + (size_t)(t0 + 8) * CC + c) = o1;
        }
    }
}

// ---------------------------------------------------------------------------
// Launch (4 kernels -> ncu -s 5 -c 1 lands on the GEMM again)
// ---------------------------------------------------------------------------
extern "C" void kernel_launch(void* const* d_in, const int* in_sizes, int n_in,
                              void* d_out, int out_size) {
    const float* x     = (const float*)d_in[0];
    const float* ln_w  = (const float*)d_in[1];
    const float* ln_b  = (const float*)d_in[2];
    const float* lin_w = (const float*)d_in[3];
    const float* lin_b = (const float*)d_in[4];
    float* out = (float*)d_out;

    cudaFuncSetAttribute(gemm_f16, cudaFuncAttributeMaxDynamicSharedMemorySize, GSMEM);

    reduce_conv_kernel<<<BB * RED_CHUNKS + 1024, 256>>>(x, lin_w);
    stats_kernel<<<1, 64>>>();
    normalize_t_kernel<<<dim3(SS / 32, CC / 32, BB), dim3(32, 8)>>>(x, ln_w, ln_b);

    // M=1024 (8 x 128), N=32768 (128 x 256)
    gemm_f16<<<dim3(8, 128), 256, GSMEM>>>(lin_b, x, out);
}

// round 10
// speedup vs baseline: 1.0977x; 1.0977x over previous
#include <cuda_runtime.h>
#include <cuda_fp16.h>
#include <cstdint>

// Problem constants
#define BB 64
#define SS 1024
#define CC 512
#define SC (SS*CC)
#define NN (BB*CC)          // 32768 = total N of the big GEMM
#define EPS 1e-5f
#define RED_CHUNKS 64
#define BK 32               // k-tile (halves)
#define NT (SS / BK)        // 32 k-tiles

// Scratch (device globals; 16B-aligned for cp.async / uint4)
__device__ float2 g_partials[BB * RED_CHUNKS];
__device__ float2 g_stats[BB];
// K-panel layouts: [(kt*ROWS + row)*32 + ks], fp16
__device__ __align__(16) __half g_Hp[(size_t)NN * SS];     // B panels (64MB)
__device__ __align__(16) __half g_Wh[(size_t)SS * SS];     // A panels (2MB)

// ---------------------------------------------------------------------------
// helpers
// ---------------------------------------------------------------------------
__device__ __forceinline__ uint32_t smem_to_u32(const void* p) {
    uint32_t a;
    asm("{ .reg .u64 t; cvta.to.shared.u64 t, %1; cvt.u32.u64 %0, t; }" : "=r"(a) : "l"(p));
    return a;
}
__device__ __forceinline__ void ldmatrix_x4(uint32_t& r0, uint32_t& r1,
                                            uint32_t& r2, uint32_t& r3, uint32_t addr) {
    asm volatile("ldmatrix.sync.aligned.m8n8.x4.shared.b16 {%0,%1,%2,%3}, [%4];"
                 : "=r"(r0), "=r"(r1), "=r"(r2), "=r"(r3) : "r"(addr));
}
__device__ __forceinline__ void mma_f16(float* d, const uint32_t* a,
                                        uint32_t b0, uint32_t b1) {
    asm volatile(
        "mma.sync.aligned.m16n8k16.row.col.f32.f16.f16.f32 "
        "{%0,%1,%2,%3}, {%4,%5,%6,%7}, {%8,%9}, {%0,%1,%2,%3};"
        : "+f"(d[0]), "+f"(d[1]), "+f"(d[2]), "+f"(d[3])
        : "r"(a[0]), "r"(a[1]), "r"(a[2]), "r"(a[3]), "r"(b0), "r"(b1));
}
__device__ __forceinline__ void cp16(uint32_t dst, const void* src) {
    asm volatile("cp.async.cg.shared.global [%0], [%1], 16;" :: "r"(dst), "l"(src));
}
#define CP_COMMIT() asm volatile("cp.async.commit_group;" ::: "memory")
#define CP_WAIT1()  asm volatile("cp.async.wait_group 1;" ::: "memory")

__device__ __forceinline__ uint32_t pack2(float a, float b) {
    __half2 h = __floats2half2_rn(a, b);
    return *reinterpret_cast<uint32_t*>(&h);
}

// ---------------------------------------------------------------------------
// Kernel 1 (fused): blocks [0,4096): per-batch partial sums.
//                   blocks [4096,5120): convert W -> g_Wh fp16 K-panels.
// ---------------------------------------------------------------------------
__global__ void reduce_conv_kernel(const float* __restrict__ x,
                                   const float* __restrict__ W) {
    if (blockIdx.x < BB * RED_CHUNKS) {
        const int b     = blockIdx.x / RED_CHUNKS;
        const int chunk = blockIdx.x % RED_CHUNKS;
        const int n4    = SC / RED_CHUNKS / 4;
        const float4* px = reinterpret_cast<const float4*>(x + (size_t)b * SC) + (size_t)chunk * n4;

        float s = 0.f, sq = 0.f;
        for (int i = threadIdx.x; i < n4; i += blockDim.x) {
            float4 v = px[i];
            s  += v.x + v.y + v.z + v.w;
            sq += v.x*v.x + v.y*v.y + v.z*v.z + v.w*v.w;
        }
        __shared__ float ss[8], ssq[8];
        #pragma unroll
        for (int o = 16; o > 0; o >>= 1) {
            s  += __shfl_down_sync(0xffffffff, s,  o);
            sq += __shfl_down_sync(0xffffffff, sq, o);
        }
        if ((threadIdx.x & 31) == 0) { ss[threadIdx.x >> 5] = s; ssq[threadIdx.x >> 5] = sq; }
        __syncthreads();
        if (threadIdx.x == 0) {
            float ts = 0.f, tsq = 0.f;
            #pragma unroll
            for (int w = 0; w < 8; w++) { ts += ss[w]; tsq += ssq[w]; }
            g_partials[blockIdx.x] = make_float2(ts, tsq);
        }
    } else {
        // convert W (fp32 [m][s]) -> g_Wh fp16 K-panels [(kt*1024+m)*32+ks]
        __shared__ float tile[32][33];
        const int cw = blockIdx.x - BB * RED_CHUNKS;   // 0..1023
        const int m0 = (cw >> 5) * 32;
        const int s0 = (cw & 31) * 32;
        const int tx = threadIdx.x & 31;
        const int ty = threadIdx.x >> 5;
        #pragma unroll
        for (int i = 0; i < 4; i++)
            tile[ty + i * 8][tx] = W[(size_t)(m0 + ty + i * 8) * SS + s0 + tx];
        __syncthreads();
        const int idx = threadIdx.x;
        if (idx < 128) {
            const int m     = idx >> 2;
            const int chunk = idx & 3;
            const int kt    = s0 >> 5;
            uint4 pk;
            pk.x = pack2(tile[m][chunk*8+0], tile[m][chunk*8+1]);
            pk.y = pack2(tile[m][chunk*8+2], tile[m][chunk*8+3]);
            pk.z = pack2(tile[m][chunk*8+4], tile[m][chunk*8+5]);
            pk.w = pack2(tile[m][chunk*8+6], tile[m][chunk*8+7]);
            *reinterpret_cast<uint4*>(g_Wh + ((size_t)kt * SS + m0 + m) * 32 + chunk * 8) = pk;
        }
    }
}

// ---------------------------------------------------------------------------
// Kernel 2: finalize stats (mu, rstd) per batch.
// ---------------------------------------------------------------------------
__global__ void stats_kernel() {
    int b = threadIdx.x;
    if (b < BB) {
        float s = 0.f, sq = 0.f;
        #pragma unroll 8
        for (int i = 0; i < RED_CHUNKS; i++) {
            float2 p = g_partials[b * RED_CHUNKS + i];
            s += p.x; sq += p.y;
        }
        float mu  = s / (float)SC;
        float var = fmaxf(sq / (float)SC - mu * mu, 0.f);
        g_stats[b] = make_float2(mu, rsqrtf(var + EPS));
    }
}

// ---------------------------------------------------------------------------
// Kernel 3: fused LayerNorm + transpose -> g_Hp K-panels [(kt*NN + n)*32 + ks].
// ---------------------------------------------------------------------------
__global__ void normalize_t_kernel(const float* __restrict__ x,
                                   const float* __restrict__ lnw,
                                   const float* __restrict__ lnb) {
    __shared__ float tile[32][33];     // [s_local][c_local]
    const int b  = blockIdx.z;
    const int s0 = blockIdx.x * 32;
    const int c0 = blockIdx.y * 32;
    const float2 st = g_stats[b];

    #pragma unroll
    for (int i = 0; i < 4; i++) {
        int s = s0 + threadIdx.y + i * 8;
        int c = c0 + threadIdx.x;
        float v  = x  [(size_t)b * SC + (size_t)s * CC + c];
        float w  = lnw[(size_t)s * CC + c];
        float bb = lnb[(size_t)s * CC + c];
        tile[threadIdx.y + i * 8][threadIdx.x] = (v - st.x) * st.y * w + bb;
    }
    __syncthreads();
    const int idx = threadIdx.y * 32 + threadIdx.x;
    if (idx < 128) {
        const int c     = idx >> 2;
        const int chunk = idx & 3;
        const int kt    = s0 >> 5;
        const int n     = b * CC + c0 + c;
        uint4 pk;
        pk.x = pack2(tile[chunk*8+0][c], tile[chunk*8+1][c]);
        pk.y = pack2(tile[chunk*8+2][c], tile[chunk*8+3][c]);
        pk.z = pack2(tile[chunk*8+4][c], tile[chunk*8+5][c]);
        pk.w = pack2(tile[chunk*8+6][c], tile[chunk*8+7][c]);
        *reinterpret_cast<uint4*>(g_Hp + ((size_t)kt * NN + n) * 32 + chunk * 8) = pk;
    }
}

// ---------------------------------------------------------------------------
// Kernel 4: fp16 GEMM, fp32 acc. D[1024, 32768] = Wh x Hp^T, K=1024.
// CTA 128(M) x 128(N) x 32(K). 8 warps (2M x 4N), warp 64x32.
// __launch_bounds__(256, 2) -> <=128 regs -> 2 CTAs/SM (independent barriers
// interleave at sync points; this is the occupancy latency-hiding R7 lacked).
// 3-stage cp.async pipeline, 80B smem rows (conflict-free ldmatrix).
// Epilogue: out = x + relu(D + bias).
// ---------------------------------------------------------------------------
#define BM 128
#define BN 128
#define AST (BM * 80)              // 10240 B per A stage
#define BST (BN * 80)              // 10240 B per B stage
#define NSTG 3
#define OFF_BS (NSTG * AST)        // B stages base
#define GSMEM (NSTG * (AST + BST)) // 61440 B -> 2 CTAs = 120KB of 228KB

__global__ __launch_bounds__(256, 2)
void gemm_f16(const float* __restrict__ linb,
              const float* __restrict__ x, float* __restrict__ out)
{
    extern __shared__ char smem[];
    const uint32_t sb = smem_to_u32(smem);

    const int tid  = threadIdx.x;
    const int lane = tid & 31;
    const int wid  = tid >> 5;
    const int wm   = (wid >> 2) * 64;       // 0 / 64
    const int wn   = (wid & 3) * 32;        // 0..96
    const int m0   = blockIdx.x * BM;
    const int n0   = blockIdx.y * BN;

    float acc[4][4][4];
    #pragma unroll
    for (int i = 0; i < 4; i++)
        #pragma unroll
        for (int j = 0; j < 4; j++)
            #pragma unroll
            for (int k = 0; k < 4; k++) acc[i][j][k] = 0.f;

    // cp.async mapping: 128 rows x 4 chunks = 512 tasks -> 2/thread (adjacent)
    const int ldRow = tid >> 1;
    const int ldPrt = (tid & 1) * 2;

    const __half* Apan = g_Wh + ((size_t)m0) * 32;  // + t*SS*32 per tile
    const __half* Bpan = g_Hp + ((size_t)n0) * 32;  // + t*NN*32 per tile

    #define ISSUE(t, st)                                                          \
        do {                                                                      \
            const __half* asrc = Apan + (size_t)(t) * SS * 32;                    \
            const __half* bsrc = Bpan + (size_t)(t) * NN * 32;                    \
            _Pragma("unroll")                                                     \
            for (int cc = 0; cc < 2; cc++) {                                      \
                cp16(sb + (st) * AST + ldRow * 80 + (ldPrt + cc) * 16,            \
                     asrc + (size_t)ldRow * 32 + (ldPrt + cc) * 8);               \
                cp16(sb + OFF_BS + (st) * BST + ldRow * 80 + (ldPrt + cc) * 16,   \
                     bsrc + (size_t)ldRow * 32 + (ldPrt + cc) * 8);               \
            }                                                                     \
        } while (0)

    // ldmatrix base addresses
    const int l15 = lane & 15;
    const int lhi = lane >> 4;
    const uint32_t aLd = sb + (wm + l15) * 80 + lhi * 16;
    const uint32_t bLd = sb + OFF_BS + (wn + l15) * 80 + lhi * 16;

    // prologue: stages 0,1
    ISSUE(0, 0); CP_COMMIT();
    ISSUE(1, 1); CP_COMMIT();

    for (int t = 0; t < NT; t++) {
        const int st = t % 3;
        CP_WAIT1();                 // tile t complete (newest group may pend)
        __syncthreads();
        if (t + 2 < NT) ISSUE(t + 2, (t + 2) % 3);
        CP_COMMIT();                // unconditional: keeps wait_group counting

        #pragma unroll
        for (int ks = 0; ks < 2; ks++) {
            uint32_t a[4][4], bm_[2][4];
            #pragma unroll
            for (int i = 0; i < 4; i++)
                ldmatrix_x4(a[i][0], a[i][1], a[i][2], a[i][3],
                            aLd + st * AST + i * 16 * 80 + ks * 32);
            #pragma unroll
            for (int j = 0; j < 2; j++)
                ldmatrix_x4(bm_[j][0], bm_[j][1], bm_[j][2], bm_[j][3],
                            bLd + st * BST + j * 16 * 80 + ks * 32);
            #pragma unroll
            for (int i = 0; i < 4; i++)
                #pragma unroll
                for (int j = 0; j < 2; j++) {
                    mma_f16(acc[i][2*j    ], a[i], bm_[j][0], bm_[j][2]);
                    mma_f16(acc[i][2*j + 1], a[i], bm_[j][1], bm_[j][3]);
                }
        }
    }

    // Epilogue: n -> (batch, channel); whole CTA sits in one batch.
    const int bidx = n0 >> 9;
    const int c0   = n0 & 511;
    const float* xb = x   + (size_t)bidx * SC;
    float*       ob = out + (size_t)bidx * SC;

    #pragma unroll
    for (int i = 0; i < 4; i++) {
        const int t0 = m0 + wm + i * 16 + (lane >> 2);
        const float bias0 = __ldg(linb + t0);
        const float bias1 = __ldg(linb + t0 + 8);
        #pragma unroll
        for (int j = 0; j < 4; j++) {
            const int c = c0 + wn + j * 8 + (lane & 3) * 2;
            float2 xv0 = *reinterpret_cast<const float2*>(xb + (size_t)t0 * CC + c);
            float2 o0;
            o0.x = xv0.x + fmaxf(acc[i][j][0] + bias0, 0.f);
            o0.y = xv0.y + fmaxf(acc[i][j][1] + bias0, 0.f);
            *reinterpret_cast<float2*>(ob + (size_t)t0 * CC + c) = o0;

            float2 xv1 = *reinterpret_cast<const float2*>(xb + (size_t)(t0 + 8) * CC + c);
            float2 o1;
            o1.x = xv1.x + fmaxf(acc[i][j][2] + bias1, 0.f);
            o1.y = xv1.y + fmaxf(acc[i][j][3] + bias1, 0.f);
            *reinterpret_cast<float2*>(ob + (size_t)(t0 + 8) * CC + c) = o1;
        }
    }
}

// ---------------------------------------------------------------------------
// Launch (4 kernels so ncu -s 5 -c 1 lands on the GEMM)
// ---------------------------------------------------------------------------
extern "C" void kernel_launch(void* const* d_in, const int* in_sizes, int n_in,
                              void* d_out, int out_size) {
    const float* x     = (const float*)d_in[0];
    const float* ln_w  = (const float*)d_in[1];
    const float* ln_b  = (const float*)d_in[2];
    const float* lin_w = (const float*)d_in[3];
    const float* lin_b = (const float*)d_in[4];
    float* out = (float*)d_out;

    cudaFuncSetAttribute(gemm_f16, cudaFuncAttributeMaxDynamicSharedMemorySize, GSMEM);

    reduce_conv_kernel<<<BB * RED_CHUNKS + 1024, 256>>>(x, lin_w);
    stats_kernel<<<1, 64>>>();
    normalize_t_kernel<<<dim3(SS / 32, CC / 32, BB), dim3(32, 8)>>>(x, ln_w, ln_b);

    // M=1024 (8 x 128), N=32768 (256 x 128)
    gemm_f16<<<dim3(8, 256), 256, GSMEM>>>(lin_b, x, out);
}

// round 11
// speedup vs baseline: 1.4544x; 1.3250x over previous
#include <cuda_runtime.h>
#include <cuda_fp16.h>
#include <cstdint>

// Problem constants
#define BB 64
#define SS 1024
#define CC 512
#define SC (SS*CC)
#define NN (BB*CC)          // 32768 = total N of the big GEMM
#define EPS 1e-5f
#define RED_CHUNKS 64
#define BK 32               // k-tile (halves)
#define NT (SS / BK)        // 32 k-tiles

// Scratch (device globals; 16B-aligned for cp.async / uint4)
__device__ float2 g_partials[BB * RED_CHUNKS];
__device__ float2 g_stats[BB];
// K-panel layouts: [(kt*ROWS + row)*32 + ks], fp16
__device__ __align__(16) __half g_Hp[(size_t)NN * SS];     // B panels (64MB)
__device__ __align__(16) __half g_Wh[(size_t)SS * SS];     // A panels (2MB)

// ---------------------------------------------------------------------------
// helpers
// ---------------------------------------------------------------------------
__device__ __forceinline__ uint32_t smem_to_u32(const void* p) {
    uint32_t a;
    asm("{ .reg .u64 t; cvta.to.shared.u64 t, %1; cvt.u32.u64 %0, t; }" : "=r"(a) : "l"(p));
    return a;
}
__device__ __forceinline__ void ldmatrix_x4(uint32_t& r0, uint32_t& r1,
                                            uint32_t& r2, uint32_t& r3, uint32_t addr) {
    asm volatile("ldmatrix.sync.aligned.m8n8.x4.shared.b16 {%0,%1,%2,%3}, [%4];"
                 : "=r"(r0), "=r"(r1), "=r"(r2), "=r"(r3) : "r"(addr));
}
__device__ __forceinline__ void mma_f16(float* d, const uint32_t* a,
                                        uint32_t b0, uint32_t b1) {
    asm volatile(
        "mma.sync.aligned.m16n8k16.row.col.f32.f16.f16.f32 "
        "{%0,%1,%2,%3}, {%4,%5,%6,%7}, {%8,%9}, {%0,%1,%2,%3};"
        : "+f"(d[0]), "+f"(d[1]), "+f"(d[2]), "+f"(d[3])
        : "r"(a[0]), "r"(a[1]), "r"(a[2]), "r"(a[3]), "r"(b0), "r"(b1));
}
__device__ __forceinline__ void cp16(uint32_t dst, const void* src) {
    asm volatile("cp.async.cg.shared.global [%0], [%1], 16;" :: "r"(dst), "l"(src));
}
#define CP_COMMIT() asm volatile("cp.async.commit_group;" ::: "memory")
#define CP_WAIT1()  asm volatile("cp.async.wait_group 1;" ::: "memory")

__device__ __forceinline__ uint32_t pack2(float a, float b) {
    __half2 h = __floats2half2_rn(a, b);
    return *reinterpret_cast<uint32_t*>(&h);
}

// ---------------------------------------------------------------------------
// Kernel 1 (fused): blocks [0,4096): per-batch partial sums.
//                   blocks [4096,5120): convert W -> g_Wh fp16 K-panels.
// ---------------------------------------------------------------------------
__global__ void reduce_conv_kernel(const float* __restrict__ x,
                                   const float* __restrict__ W) {
    if (blockIdx.x < BB * RED_CHUNKS) {
        const int b     = blockIdx.x / RED_CHUNKS;
        const int chunk = blockIdx.x % RED_CHUNKS;
        const int n4    = SC / RED_CHUNKS / 4;
        const float4* px = reinterpret_cast<const float4*>(x + (size_t)b * SC) + (size_t)chunk * n4;

        float s = 0.f, sq = 0.f;
        for (int i = threadIdx.x; i < n4; i += blockDim.x) {
            float4 v = px[i];
            s  += v.x + v.y + v.z + v.w;
            sq += v.x*v.x + v.y*v.y + v.z*v.z + v.w*v.w;
        }
        __shared__ float ss[8], ssq[8];
        #pragma unroll
        for (int o = 16; o > 0; o >>= 1) {
            s  += __shfl_down_sync(0xffffffff, s,  o);
            sq += __shfl_down_sync(0xffffffff, sq, o);
        }
        if ((threadIdx.x & 31) == 0) { ss[threadIdx.x >> 5] = s; ssq[threadIdx.x >> 5] = sq; }
        __syncthreads();
        if (threadIdx.x == 0) {
            float ts = 0.f, tsq = 0.f;
            #pragma unroll
            for (int w = 0; w < 8; w++) { ts += ss[w]; tsq += ssq[w]; }
            g_partials[blockIdx.x] = make_float2(ts, tsq);
        }
    } else {
        __shared__ float tile[32][33];
        const int cw = blockIdx.x - BB * RED_CHUNKS;   // 0..1023
        const int m0 = (cw >> 5) * 32;
        const int s0 = (cw & 31) * 32;
        const int tx = threadIdx.x & 31;
        const int ty = threadIdx.x >> 5;
        #pragma unroll
        for (int i = 0; i < 4; i++)
            tile[ty + i * 8][tx] = W[(size_t)(m0 + ty + i * 8) * SS + s0 + tx];
        __syncthreads();
        const int idx = threadIdx.x;
        if (idx < 128) {
            const int m     = idx >> 2;
            const int chunk = idx & 3;
            const int kt    = s0 >> 5;
            uint4 pk;
            pk.x = pack2(tile[m][chunk*8+0], tile[m][chunk*8+1]);
            pk.y = pack2(tile[m][chunk*8+2], tile[m][chunk*8+3]);
            pk.z = pack2(tile[m][chunk*8+4], tile[m][chunk*8+5]);
            pk.w = pack2(tile[m][chunk*8+6], tile[m][chunk*8+7]);
            *reinterpret_cast<uint4*>(g_Wh + ((size_t)kt * SS + m0 + m) * 32 + chunk * 8) = pk;
        }
    }
}

// ---------------------------------------------------------------------------
// Kernel 2: finalize stats (mu, rstd) per batch.
// ---------------------------------------------------------------------------
__global__ void stats_kernel() {
    int b = threadIdx.x;
    if (b < BB) {
        float s = 0.f, sq = 0.f;
        #pragma unroll 8
        for (int i = 0; i < RED_CHUNKS; i++) {
            float2 p = g_partials[b * RED_CHUNKS + i];
            s += p.x; sq += p.y;
        }
        float mu  = s / (float)SC;
        float var = fmaxf(sq / (float)SC - mu * mu, 0.f);
        g_stats[b] = make_float2(mu, rsqrtf(var + EPS));
    }
}

// ---------------------------------------------------------------------------
// Kernel 3: fused LayerNorm + transpose -> g_Hp K-panels [(kt*NN + n)*32 + ks].
// ---------------------------------------------------------------------------
__global__ void normalize_t_kernel(const float* __restrict__ x,
                                   const float* __restrict__ lnw,
                                   const float* __restrict__ lnb) {
    __shared__ float tile[32][33];     // [s_local][c_local]
    const int b  = blockIdx.z;
    const int s0 = blockIdx.x * 32;
    const int c0 = blockIdx.y * 32;
    const float2 st = g_stats[b];

    #pragma unroll
    for (int i = 0; i < 4; i++) {
        int s = s0 + threadIdx.y + i * 8;
        int c = c0 + threadIdx.x;
        float v  = x  [(size_t)b * SC + (size_t)s * CC + c];
        float w  = lnw[(size_t)s * CC + c];
        float bb = lnb[(size_t)s * CC + c];
        tile[threadIdx.y + i * 8][threadIdx.x] = (v - st.x) * st.y * w + bb;
    }
    __syncthreads();
    const int idx = threadIdx.y * 32 + threadIdx.x;
    if (idx < 128) {
        const int c     = idx >> 2;
        const int chunk = idx & 3;
        const int kt    = s0 >> 5;
        const int n     = b * CC + c0 + c;
        uint4 pk;
        pk.x = pack2(tile[chunk*8+0][c], tile[chunk*8+1][c]);
        pk.y = pack2(tile[chunk*8+2][c], tile[chunk*8+3][c]);
        pk.z = pack2(tile[chunk*8+4][c], tile[chunk*8+5][c]);
        pk.w = pack2(tile[chunk*8+6][c], tile[chunk*8+7][c]);
        *reinterpret_cast<uint4*>(g_Hp + ((size_t)kt * NN + n) * 32 + chunk * 8) = pk;
    }
}

// ---------------------------------------------------------------------------
// Kernel 4: fp16 GEMM, fp32 acc. D[1024, 32768] = Wh x Hp^T, K=1024.
// CTA 128(M) x 128(N) x 32(K). 128 threads, 4 warps (2M x 2N), warp 64x64
// (minimal fragment bytes/FMA). Register fragment DOUBLE-BUFFER: load ks+1
// fragments while MMAs for ks run -> hides LDSM latency inside each warp.
// 2 CTAs/SM (regs ~225, launch_bounds(128,2)). 3-stage cp.async pipeline.
// smem rows 80B (conflict-free ldmatrix). Epilogue: out = x + relu(D + bias).
// ---------------------------------------------------------------------------
#define BM 128
#define BN 128
#define AST (BM * 80)              // 10240 B per A stage
#define BST (BN * 80)              // 10240 B per B stage
#define NSTG 3
#define OFF_BS (NSTG * AST)        // B stages base
#define GSMEM (NSTG * (AST + BST)) // 61440 B -> 2 CTAs = 120KB

__global__ __launch_bounds__(128, 2)
void gemm_f16(const float* __restrict__ linb,
              const float* __restrict__ x, float* __restrict__ out)
{
    extern __shared__ char smem[];
    const uint32_t sb = smem_to_u32(smem);

    const int tid  = threadIdx.x;
    const int lane = tid & 31;
    const int wid  = tid >> 5;          // 0..3
    const int wm   = (wid >> 1) * 64;   // 0 / 64
    const int wn   = (wid & 1) * 64;    // 0 / 64
    const int m0   = blockIdx.x * BM;
    const int n0   = blockIdx.y * BN;

    float acc[4][8][4];
    #pragma unroll
    for (int i = 0; i < 4; i++)
        #pragma unroll
        for (int j = 0; j < 8; j++)
            #pragma unroll
            for (int k = 0; k < 4; k++) acc[i][j][k] = 0.f;

    const __half* Apan = g_Wh + ((size_t)m0) * 32;  // + t*SS*32 per tile
    const __half* Bpan = g_Hp + ((size_t)n0) * 32;  // + t*NN*32 per tile

    // cp.async: 512 A tasks + 512 B tasks over 128 threads = 4+4 per thread.
    // task idx = k*128 + tid: row = idx>>2 (0..127), chunk = idx&3.
    #define ISSUE(t, st)                                                          \
        do {                                                                      \
            const __half* asrc = Apan + (size_t)(t) * SS * 32;                    \
            const __half* bsrc = Bpan + (size_t)(t) * NN * 32;                    \
            _Pragma("unroll")                                                     \
            for (int k = 0; k < 4; k++) {                                         \
                int idx = k * 128 + tid;                                          \
                int row = idx >> 2, ch = idx & 3;                                 \
                cp16(sb + (st) * AST + row * 80 + ch * 16,                        \
                     asrc + (size_t)row * 32 + ch * 8);                           \
                cp16(sb + OFF_BS + (st) * BST + row * 80 + ch * 16,               \
                     bsrc + (size_t)row * 32 + ch * 8);                           \
            }                                                                     \
        } while (0)

    // ldmatrix base addresses (row l15 within warp tile, 16B half-row lhi)
    const int l15 = lane & 15;
    const int lhi = lane >> 4;
    const uint32_t aLd = sb + (wm + l15) * 80 + lhi * 16;
    const uint32_t bLd = sb + OFF_BS + (wn + l15) * 80 + lhi * 16;

    // fragment double buffers
    uint32_t af[2][16], bf[2][16];

    #define LOAD_FRAGS(buf, st, ks)                                               \
        do {                                                                      \
            _Pragma("unroll")                                                     \
            for (int i = 0; i < 4; i++)                                           \
                ldmatrix_x4(af[buf][i*4+0], af[buf][i*4+1],                       \
                            af[buf][i*4+2], af[buf][i*4+3],                       \
                            aLd + (st) * AST + i * 16 * 80 + (ks) * 32);          \
            _Pragma("unroll")                                                     \
            for (int j = 0; j < 4; j++)                                           \
                ldmatrix_x4(bf[buf][j*4+0], bf[buf][j*4+1],                       \
                            bf[buf][j*4+2], bf[buf][j*4+3],                       \
                            bLd + (st) * BST + j * 16 * 80 + (ks) * 32);          \
        } while (0)

    #define MMA_ALL(buf)                                                          \
        do {                                                                      \
            _Pragma("unroll")                                                     \
            for (int i = 0; i < 4; i++)                                           \
                _Pragma("unroll")                                                 \
                for (int j = 0; j < 4; j++) {                                     \
                    mma_f16(acc[i][2*j    ], &af[buf][i*4],                       \
                            bf[buf][j*4+0], bf[buf][j*4+2]);                      \
                    mma_f16(acc[i][2*j + 1], &af[buf][i*4],                       \
                            bf[buf][j*4+1], bf[buf][j*4+3]);                      \
                }                                                                 \
        } while (0)

    // prologue: stages 0,1 in flight; stage 0 ready; frags(0, ks=0) loaded.
    ISSUE(0, 0); CP_COMMIT();
    ISSUE(1, 1); CP_COMMIT();
    CP_WAIT1();
    __syncthreads();
    LOAD_FRAGS(0, 0, 0);

    for (int t = 0; t < NT; t++) {
        const int st = t % 3;

        // ks = 0 phase: prefetch ks=1 frags, then MMA on ks=0 frags.
        LOAD_FRAGS(1, st, 1);
        MMA_ALL(0);

        // ks = 1 phase: keep gmem pipe fed, advance stage, prefetch next
        // tile's ks=0 frags, then MMA on ks=1 frags.
        if (t + 2 < NT) ISSUE(t + 2, (t + 2) % 3);
        CP_COMMIT();                // unconditional: keeps wait_group ledger
        if (t + 1 < NT) {
            CP_WAIT1();             // tile t+1's stage complete
            __syncthreads();        // all threads' cp.async visible; all warps
                                    // past their stage-(t-1) fragment reads
            LOAD_FRAGS(0, (t + 1) % 3, 0);
        }
        MMA_ALL(1);
    }

    // Epilogue: n -> (batch, channel); whole CTA sits in one batch.
    const int bidx = n0 >> 9;
    const int c0   = n0 & 511;
    const float* xb = x   + (size_t)bidx * SC;
    float*       ob = out + (size_t)bidx * SC;

    #pragma unroll
    for (int i = 0; i < 4; i++) {
        const int t0 = m0 + wm + i * 16 + (lane >> 2);
        const float bias0 = __ldg(linb + t0);
        const float bias1 = __ldg(linb + t0 + 8);
        #pragma unroll
        for (int j = 0; j < 8; j++) {
            const int c = c0 + wn + j * 8 + (lane & 3) * 2;
            float2 xv0 = *reinterpret_cast<const float2*>(xb + (size_t)t0 * CC + c);
            float2 o0;
            o0.x = xv0.x + fmaxf(acc[i][j][0] + bias0, 0.f);
            o0.y = xv0.y + fmaxf(acc[i][j][1] + bias0, 0.f);
            *reinterpret_cast<float2*>(ob + (size_t)t0 * CC + c) = o0;

            float2 xv1 = *reinterpret_cast<const float2*>(xb + (size_t)(t0 + 8) * CC + c);
            float2 o1;
            o1.x = xv1.x + fmaxf(acc[i][j][2] + bias1, 0.f);
            o1.y = xv1.y + fmaxf(acc[i][j][3] + bias1, 0.f);
            *reinterpret_cast<float2*>(ob + (size_t)(t0 + 8) * CC + c) = o1;
        }
    }
}

// ---------------------------------------------------------------------------
// Launch (4 kernels so ncu -s 5 -c 1 lands on the GEMM)
// ---------------------------------------------------------------------------
extern "C" void kernel_launch(void* const* d_in, const int* in_sizes, int n_in,
                              void* d_out, int out_size) {
    const float* x     = (const float*)d_in[0];
    const float* ln_w  = (const float*)d_in[1];
    const float* ln_b  = (const float*)d_in[2];
    const float* lin_w = (const float*)d_in[3];
    const float* lin_b = (const float*)d_in[4];
    float* out = (float*)d_out;

    cudaFuncSetAttribute(gemm_f16, cudaFuncAttributeMaxDynamicSharedMemorySize, GSMEM);

    reduce_conv_kernel<<<BB * RED_CHUNKS + 1024, 256>>>(x, lin_w);
    stats_kernel<<<1, 64>>>();
    normalize_t_kernel<<<dim3(SS / 32, CC / 32, BB), dim3(32, 8)>>>(x, ln_w, ln_b);

    // M=1024 (8 x 128), N=32768 (256 x 128)
    gemm_f16<<<dim3(8, 256), 128, GSMEM>>>(lin_b, x, out);
}